// round 1
// baseline (speedup 1.0000x reference)
#include <cuda_runtime.h>

// Bilinear attention: B=8, S=2048, H=1024 (fp32)
//   xw     = x @ W            [B,S,H]
//   scores = xw @ x^T         [B,S,S]
//   attn   = softmax(scores)  [B,S,S]
//   ctx    = attn @ x         [B,S,H]
// Outputs packed into d_out as (context, attn): ctx at offset 0 (16.78M floats),
// attn at offset 16777216 (33.55M floats).

#define BM 128
#define BN 128
#define BK 16

// Scratch for XW: 8*2048*1024 floats = 64 MiB (device global, no allocation).
__device__ float g_xw[8ull * 2048ull * 1024ull];

// C[M,N] = A[M,K] @ B, batched over blockIdx.z.
// TRANS_B=false: B is [K,N] row-major.  TRANS_B=true: B is [N,K] row-major (NT).
// All of M,N,K are multiples of 128 here, so no bounds checks.
template <bool TRANS_B>
__global__ __launch_bounds__(256)
void sgemm(const float* __restrict__ Ag, const float* __restrict__ Bg,
           float* __restrict__ Cg, int M, int N, int K,
           long long sA, long long sB, long long sC)
{
    __shared__ float As[BK][BM + 4];  // +4 pad: cuts store bank conflicts
    __shared__ float Bs[BK][BN];

    const int tid = threadIdx.x;
    const int bx = blockIdx.x, by = blockIdx.y, bz = blockIdx.z;

    const float* A = Ag + bz * sA + (long long)by * BM * K;
    const float* B;
    if (TRANS_B) B = Bg + bz * sB + (long long)bx * BN * K;
    else         B = Bg + bz * sB + bx * BN;
    float* C = Cg + bz * sC + (long long)by * BM * N + bx * BN;

    // A (and NT-B) tile loaders: 128 rows x 16 cols as float4, 2 per thread
    const int arow = tid >> 2;          // 0..63
    const int acol = (tid & 3) << 2;    // 0,4,8,12
    // NN-B tile loader: 16 rows x 128 cols as float4, 2 per thread
    const int brow = tid >> 5;          // 0..7
    const int bcol = (tid & 31) << 2;   // 0..124

    const int ty = tid >> 4;            // 0..15
    const int tx = tid & 15;            // 0..15

    float acc[8][8];
#pragma unroll
    for (int i = 0; i < 8; ++i)
#pragma unroll
        for (int j = 0; j < 8; ++j) acc[i][j] = 0.f;

    for (int kt = 0; kt < K; kt += BK) {
#pragma unroll
        for (int i = 0; i < 2; ++i) {
            int r = arow + i * 64;
            float4 v = *(const float4*)(A + (long long)r * K + kt + acol);
            As[acol + 0][r] = v.x;
            As[acol + 1][r] = v.y;
            As[acol + 2][r] = v.z;
            As[acol + 3][r] = v.w;
        }
        if (TRANS_B) {
#pragma unroll
            for (int i = 0; i < 2; ++i) {
                int r = arow + i * 64;
                float4 v = *(const float4*)(B + (long long)r * K + kt + acol);
                Bs[acol + 0][r] = v.x;
                Bs[acol + 1][r] = v.y;
                Bs[acol + 2][r] = v.z;
                Bs[acol + 3][r] = v.w;
            }
        } else {
#pragma unroll
            for (int i = 0; i < 2; ++i) {
                int r = brow + i * 8;
                float4 v = *(const float4*)(B + (long long)(kt + r) * N + bcol);
                *(float4*)&Bs[r][bcol] = v;
            }
        }
        __syncthreads();

#pragma unroll
        for (int k = 0; k < BK; ++k) {
            float4 a0 = *(const float4*)&As[k][ty * 4];
            float4 a1 = *(const float4*)&As[k][64 + ty * 4];
            float4 b0 = *(const float4*)&Bs[k][tx * 4];
            float4 b1 = *(const float4*)&Bs[k][64 + tx * 4];
            float a[8]  = {a0.x, a0.y, a0.z, a0.w, a1.x, a1.y, a1.z, a1.w};
            float bb[8] = {b0.x, b0.y, b0.z, b0.w, b1.x, b1.y, b1.z, b1.w};
#pragma unroll
            for (int i = 0; i < 8; ++i)
#pragma unroll
                for (int j = 0; j < 8; ++j)
                    acc[i][j] += a[i] * bb[j];
        }
        __syncthreads();
    }

#pragma unroll
    for (int i = 0; i < 8; ++i) {
        int m = (i < 4) ? (ty * 4 + i) : (64 + ty * 4 + (i - 4));
        float4 c0 = make_float4(acc[i][0], acc[i][1], acc[i][2], acc[i][3]);
        float4 c1 = make_float4(acc[i][4], acc[i][5], acc[i][6], acc[i][7]);
        *(float4*)(C + (long long)m * N + tx * 4)      = c0;
        *(float4*)(C + (long long)m * N + 64 + tx * 4) = c1;
    }
}

// In-place row softmax over rows of length 2048. One block (256 threads) per row.
__global__ __launch_bounds__(256)
void softmax_rows(float* __restrict__ data)
{
    const int S = 2048;
    float* p = data + (long long)blockIdx.x * S;
    const int tid = threadIdx.x;

    float4 v0 = ((const float4*)p)[tid];
    float4 v1 = ((const float4*)p)[tid + 256];

    float m = fmaxf(fmaxf(fmaxf(v0.x, v0.y), fmaxf(v0.z, v0.w)),
                    fmaxf(fmaxf(v1.x, v1.y), fmaxf(v1.z, v1.w)));

    __shared__ float red[8];
#pragma unroll
    for (int o = 16; o > 0; o >>= 1)
        m = fmaxf(m, __shfl_xor_sync(0xffffffffu, m, o));
    if ((tid & 31) == 0) red[tid >> 5] = m;
    __syncthreads();
    {
        float t = (tid < 8) ? red[tid & 7] : -1e30f;
#pragma unroll
        for (int o = 4; o > 0; o >>= 1)
            t = fmaxf(t, __shfl_xor_sync(0xffffffffu, t, o));
        m = __shfl_sync(0xffffffffu, t, 0);
        // broadcast warp0's result to all warps via shared
        __syncthreads();
        if (tid == 0) red[0] = m;
        __syncthreads();
        m = red[0];
    }

    v0.x = __expf(v0.x - m); v0.y = __expf(v0.y - m);
    v0.z = __expf(v0.z - m); v0.w = __expf(v0.w - m);
    v1.x = __expf(v1.x - m); v1.y = __expf(v1.y - m);
    v1.z = __expf(v1.z - m); v1.w = __expf(v1.w - m);

    float s = v0.x + v0.y + v0.z + v0.w + v1.x + v1.y + v1.z + v1.w;
#pragma unroll
    for (int o = 16; o > 0; o >>= 1)
        s += __shfl_xor_sync(0xffffffffu, s, o);
    __syncthreads();
    if ((tid & 31) == 0) red[tid >> 5] = s;
    __syncthreads();
    {
        float t = (tid < 8) ? red[tid & 7] : 0.f;
#pragma unroll
        for (int o = 4; o > 0; o >>= 1)
            t += __shfl_xor_sync(0xffffffffu, t, o);
        __syncthreads();
        if (tid == 0) red[0] = t;
        __syncthreads();
        s = red[0];
    }

    float inv = 1.0f / s;
    v0.x *= inv; v0.y *= inv; v0.z *= inv; v0.w *= inv;
    v1.x *= inv; v1.y *= inv; v1.z *= inv; v1.w *= inv;

    ((float4*)p)[tid]       = v0;
    ((float4*)p)[tid + 256] = v1;
}

extern "C" void kernel_launch(void* const* d_in, const int* in_sizes, int n_in,
                              void* d_out, int out_size)
{
    const float* x = (const float*)d_in[0];   // [8,2048,1024]
    const float* w = (const float*)d_in[1];   // [1024,1024]
    float* ctx  = (float*)d_out;                       // [8,2048,1024]
    float* attn = (float*)d_out + 16777216LL;          // [8,2048,2048]

    float* xw = nullptr;
    cudaGetSymbolAddress((void**)&xw, g_xw);

    const int B = 8, S = 2048, H = 1024;
    dim3 blk(256);

    // 1) xw = x @ W   (NN, per-batch A, shared B)
    sgemm<false><<<dim3(H / BN, S / BM, B), blk>>>(
        x, w, xw, S, H, H,
        (long long)S * H, 0LL, (long long)S * H);

    // 2) scores = xw @ x^T  (NT) -> attn buffer
    sgemm<true><<<dim3(S / BN, S / BM, B), blk>>>(
        xw, x, attn, S, S, H,
        (long long)S * H, (long long)S * H, (long long)S * S);

    // 3) softmax over last dim, in place
    softmax_rows<<<B * S, 256>>>(attn);

    // 4) ctx = attn @ x  (NN)
    sgemm<false><<<dim3(H / BN, S / BM, B), blk>>>(
        attn, x, ctx, S, H, S,
        (long long)S * S, (long long)S * H, (long long)S * H);
}

// round 3
// speedup vs baseline: 1.3680x; 1.3680x over previous
#include <cuda_runtime.h>
#include <cstdint>

// Bilinear attention B=8, S=2048, H=1024 fp32.
// GEMMs on warp-level tensor cores (mma.sync.m16n8k8.tf32, valid on plain
// sm_103 target) with the 3xTF32 split:
//   hi = fp32 with low 13 mantissa bits zeroed (exact tf32)
//   lo = cvt.rna.tf32(x - hi)
//   A@B ~= Ah@Bh + Ah@Bl + Al@Bh   (fp32 accumulate)
// All GEMMs NT (both operands K-major); W and x pre-transposed for GEMM1/3.

// ---------------- scratch (device globals; no allocation) ----------------
__device__ float g_xw[8ull * 2048ull * 1024ull];   // 64 MiB
__device__ float g_xt[8ull * 1024ull * 2048ull];   // 64 MiB  x^T per batch [H,S]
__device__ float g_wt[1024ull * 1024ull];          // 4 MiB   W^T [N,K]

// ---------------- helpers ----------------
__device__ __forceinline__ uint32_t smem_u32(const void* p) {
    uint32_t a;
    asm("{ .reg .u64 t; cvta.to.shared.u64 t, %1; cvt.u32.u64 %0, t; }" : "=r"(a) : "l"(p));
    return a;
}

#define CP_ASYNC16(dst, src) \
    asm volatile("cp.async.cg.shared.global [%0], [%1], 16;" :: "r"(dst), "l"(src) : "memory")
#define CP_COMMIT() asm volatile("cp.async.commit_group;" ::: "memory")
#define CP_WAIT(n)  asm volatile("cp.async.wait_group %0;" :: "n"(n) : "memory")

__device__ __forceinline__ void split_tf32(float x, uint32_t& hi, uint32_t& lo) {
    uint32_t h = __float_as_uint(x) & 0xFFFFE000u;
    hi = h;
    float l = x - __uint_as_float(h);
    asm("cvt.rna.tf32.f32 %0, %1;" : "=r"(lo) : "f"(l));
}

__device__ __forceinline__ void mma8(float* c, const uint32_t* a, const uint32_t* b) {
    asm volatile(
        "mma.sync.aligned.m16n8k8.row.col.f32.tf32.tf32.f32 "
        "{%0,%1,%2,%3}, {%4,%5,%6,%7}, {%8,%9}, {%0,%1,%2,%3};"
        : "+f"(c[0]), "+f"(c[1]), "+f"(c[2]), "+f"(c[3])
        : "r"(a[0]), "r"(a[1]), "r"(a[2]), "r"(a[3]), "r"(b[0]), "r"(b[1]));
}

// ---------------- GEMM: C[m,n] = sum_k A[m,k] * B[n,k] ----------------
// CTA tile 128x128, K-chunk 32. 8 warps: 2 (M) x 4 (N), warp tile 64x32.
// smem: 2 stages x (A tile + B tile), rows padded to 36 floats.
#define PAD 36
#define TILE_FLTS (128 * PAD)            // 4608 floats = 18432 B
#define SMEM_FLTS (4 * TILE_FLTS)        // A0 B0 A1 B1 = 73728 B

__global__ __launch_bounds__(256, 1)
void gemm_3xtf32(const float* __restrict__ Ag, const float* __restrict__ Bg,
                 float* __restrict__ Cg, int K, int N,
                 long long sA, long long sB, long long sC)
{
    extern __shared__ float sm[];
    const uint32_t sb = smem_u32(sm);

    const int tid  = threadIdx.x;
    const int wid  = tid >> 5;
    const int lane = tid & 31;
    const int g    = lane >> 2;     // group id 0..7
    const int tg   = lane & 3;      // thread in group

    const int wm = (wid >> 2) * 64; // warp M offset: 0 / 64
    const int wn = (wid & 3) * 32;  // warp N offset: 0/32/64/96

    const float* A = Ag + blockIdx.z * sA + (long long)(blockIdx.y * 128) * K;
    const float* B = Bg + blockIdx.z * sB + (long long)(blockIdx.x * 128) * K;

    // staging: 8x cp.async(16B) per thread per stage (A:4, B:4)
    const int lr = tid >> 3;         // 0..31
    const int lc = (tid & 7) * 4;    // 0,4,...,28

    float acc[4][4][4];
#pragma unroll
    for (int mt = 0; mt < 4; ++mt)
#pragma unroll
        for (int nt = 0; nt < 4; ++nt)
#pragma unroll
            for (int q = 0; q < 4; ++q) acc[mt][nt][q] = 0.f;

    const int nc = K >> 5;

    // prologue: stage 0
    {
        const uint32_t da = sb + (uint32_t)((lr * PAD + lc) * 4);
        const uint32_t db = da + TILE_FLTS * 4;
#pragma unroll
        for (int p = 0; p < 4; ++p) {
            const int r = lr + p * 32;
            CP_ASYNC16(da + p * 32 * PAD * 4, A + (long long)r * K + lc);
            CP_ASYNC16(db + p * 32 * PAD * 4, B + (long long)r * K + lc);
        }
        CP_COMMIT();
    }

    for (int i = 0; i < nc; ++i) {
        if (i + 1 < nc) {
            const int s = (i + 1) & 1;
            const int kt = (i + 1) << 5;
            const uint32_t da = sb + (uint32_t)((s * 2 * TILE_FLTS + lr * PAD + lc) * 4);
            const uint32_t db = da + TILE_FLTS * 4;
#pragma unroll
            for (int p = 0; p < 4; ++p) {
                const int r = lr + p * 32;
                CP_ASYNC16(da + p * 32 * PAD * 4, A + (long long)r * K + kt + lc);
                CP_ASYNC16(db + p * 32 * PAD * 4, B + (long long)r * K + kt + lc);
            }
            CP_COMMIT();
            CP_WAIT(1);
        } else {
            CP_WAIT(0);
        }
        __syncthreads();

        const float* As = sm + (i & 1) * 2 * TILE_FLTS;
        const float* Bs = As + TILE_FLTS;

#pragma unroll
        for (int ks = 0; ks < 4; ++ks) {
            const int k0 = ks * 8;

            uint32_t ahi[4][4], alo[4][4];
#pragma unroll
            for (int mt = 0; mt < 4; ++mt) {
                const int r0 = wm + mt * 16 + g;
                float a0 = As[r0 * PAD + k0 + tg];
                float a1 = As[(r0 + 8) * PAD + k0 + tg];
                float a2 = As[r0 * PAD + k0 + tg + 4];
                float a3 = As[(r0 + 8) * PAD + k0 + tg + 4];
                split_tf32(a0, ahi[mt][0], alo[mt][0]);
                split_tf32(a1, ahi[mt][1], alo[mt][1]);
                split_tf32(a2, ahi[mt][2], alo[mt][2]);
                split_tf32(a3, ahi[mt][3], alo[mt][3]);
            }

            uint32_t bhi[4][2], blo[4][2];
#pragma unroll
            for (int nt = 0; nt < 4; ++nt) {
                const int n0 = wn + nt * 8 + g;
                float b0 = Bs[n0 * PAD + k0 + tg];
                float b1 = Bs[n0 * PAD + k0 + tg + 4];
                split_tf32(b0, bhi[nt][0], blo[nt][0]);
                split_tf32(b1, bhi[nt][1], blo[nt][1]);
            }

#pragma unroll
            for (int mt = 0; mt < 4; ++mt)
#pragma unroll
                for (int nt = 0; nt < 4; ++nt) {
                    mma8(acc[mt][nt], ahi[mt], bhi[nt]);
                    mma8(acc[mt][nt], ahi[mt], blo[nt]);
                    mma8(acc[mt][nt], alo[mt], bhi[nt]);
                }
        }
        __syncthreads();
    }

    // epilogue
    float* C = Cg + blockIdx.z * sC
             + (long long)(blockIdx.y * 128 + wm) * N + blockIdx.x * 128 + wn;
#pragma unroll
    for (int mt = 0; mt < 4; ++mt) {
#pragma unroll
        for (int nt = 0; nt < 4; ++nt) {
            const int r0 = mt * 16 + g;
            const int c0 = nt * 8 + 2 * tg;
            *(float2*)&C[(long long)r0 * N + c0] =
                make_float2(acc[mt][nt][0], acc[mt][nt][1]);
            *(float2*)&C[(long long)(r0 + 8) * N + c0] =
                make_float2(acc[mt][nt][2], acc[mt][nt][3]);
        }
    }
}

// ---------------- transpose: out[c][r] = in[r][c], in is [R][C] ----------------
__global__ __launch_bounds__(256)
void transpose_rc(const float* __restrict__ in, float* __restrict__ out, int R, int C)
{
    __shared__ float t[32][33];
    const long long zo = (long long)blockIdx.z * R * C;
    in += zo; out += zo;
    const int c0 = blockIdx.x * 32, r0 = blockIdx.y * 32;
#pragma unroll
    for (int dy = 0; dy < 32; dy += 8)
        t[threadIdx.y + dy][threadIdx.x] =
            in[(long long)(r0 + threadIdx.y + dy) * C + c0 + threadIdx.x];
    __syncthreads();
#pragma unroll
    for (int dy = 0; dy < 32; dy += 8)
        out[(long long)(c0 + threadIdx.y + dy) * R + r0 + threadIdx.x] =
            t[threadIdx.x][threadIdx.y + dy];
}

// ---------------- softmax over rows of length 2048, in place ----------------
__global__ __launch_bounds__(256)
void softmax_rows(float* __restrict__ data)
{
    const int S = 2048;
    float* p = data + (long long)blockIdx.x * S;
    const int tid = threadIdx.x;

    float4 v0 = ((const float4*)p)[tid];
    float4 v1 = ((const float4*)p)[tid + 256];

    float m = fmaxf(fmaxf(fmaxf(v0.x, v0.y), fmaxf(v0.z, v0.w)),
                    fmaxf(fmaxf(v1.x, v1.y), fmaxf(v1.z, v1.w)));

    __shared__ float red[8];
#pragma unroll
    for (int o = 16; o > 0; o >>= 1) m = fmaxf(m, __shfl_xor_sync(~0u, m, o));
    if ((tid & 31) == 0) red[tid >> 5] = m;
    __syncthreads();
    {
        float t = (tid < 8) ? red[tid & 7] : -1e30f;
#pragma unroll
        for (int o = 4; o > 0; o >>= 1) t = fmaxf(t, __shfl_xor_sync(~0u, t, o));
        __syncthreads();
        if (tid == 0) red[0] = t;
        __syncthreads();
        m = red[0];
    }

    v0.x = __expf(v0.x - m); v0.y = __expf(v0.y - m);
    v0.z = __expf(v0.z - m); v0.w = __expf(v0.w - m);
    v1.x = __expf(v1.x - m); v1.y = __expf(v1.y - m);
    v1.z = __expf(v1.z - m); v1.w = __expf(v1.w - m);

    float s = v0.x + v0.y + v0.z + v0.w + v1.x + v1.y + v1.z + v1.w;
#pragma unroll
    for (int o = 16; o > 0; o >>= 1) s += __shfl_xor_sync(~0u, s, o);
    __syncthreads();
    if ((tid & 31) == 0) red[tid >> 5] = s;
    __syncthreads();
    {
        float t = (tid < 8) ? red[tid & 7] : 0.f;
#pragma unroll
        for (int o = 4; o > 0; o >>= 1) t += __shfl_xor_sync(~0u, t, o);
        __syncthreads();
        if (tid == 0) red[0] = t;
        __syncthreads();
        s = red[0];
    }

    const float inv = 1.0f / s;
    v0.x *= inv; v0.y *= inv; v0.z *= inv; v0.w *= inv;
    v1.x *= inv; v1.y *= inv; v1.z *= inv; v1.w *= inv;

    ((float4*)p)[tid]       = v0;
    ((float4*)p)[tid + 256] = v1;
}

// ---------------- launch ----------------
extern "C" void kernel_launch(void* const* d_in, const int* in_sizes, int n_in,
                              void* d_out, int out_size)
{
    const float* x = (const float*)d_in[0];   // [8,2048,1024]
    const float* w = (const float*)d_in[1];   // [1024,1024]
    float* ctx  = (float*)d_out;              // [8,2048,1024]
    float* attn = (float*)d_out + 16777216LL; // [8,2048,2048]

    float *xw, *xt, *wt;
    cudaGetSymbolAddress((void**)&xw, g_xw);
    cudaGetSymbolAddress((void**)&xt, g_xt);
    cudaGetSymbolAddress((void**)&wt, g_wt);

    const int SMEM_BYTES = SMEM_FLTS * 4;     // 73728
    cudaFuncSetAttribute(gemm_3xtf32, cudaFuncAttributeMaxDynamicSharedMemorySize, SMEM_BYTES);

    const int B = 8, S = 2048, H = 1024;
    dim3 tb(32, 8);

    // pre-transpose W -> wt [N=H][K=H] and x -> xt [H][S] per batch
    transpose_rc<<<dim3(H / 32, H / 32, 1), tb>>>(w, wt, H, H);
    transpose_rc<<<dim3(H / 32, S / 32, B), tb>>>(x, xt, S, H);

    // 1) xw = x @ W : A=x [B*S,1024], B=wt [1024,1024]
    gemm_3xtf32<<<dim3(H / 128, (B * S) / 128, 1), 256, SMEM_BYTES>>>(
        x, wt, xw, H, H, 0, 0, 0);

    // 2) scores = xw @ x^T : per batch, B=x already [N=S][K=H]
    gemm_3xtf32<<<dim3(S / 128, S / 128, B), 256, SMEM_BYTES>>>(
        xw, x, attn, H, S,
        (long long)S * H, (long long)S * H, (long long)S * S);

    // 3) softmax in place
    softmax_rows<<<B * S, 256>>>(attn);

    // 4) ctx = attn @ x : A=attn [S,S], B=xt [H,S] per batch
    gemm_3xtf32<<<dim3(H / 128, S / 128, B), 256, SMEM_BYTES>>>(
        attn, xt, ctx, S, H,
        (long long)S * S, (long long)S * H, (long long)S * H);
}